// round 15
// baseline (speedup 1.0000x reference)
#include <cuda_runtime.h>
#include <math.h>
#include <stdint.h>

#define NP  2048
#define B_  8
#define KNN 20

// ------------------- device scratch (allocation-free) -------------------
__device__ float d_xx[B_*NP];
__device__ float d_D[(size_t)B_*NP*NP];                       // 134 MB distances
__device__ int   d_idx[B_*NP*KNN];
__device__ __align__(16) float d_xT[(size_t)B_*NP*4];         // layer-1 gather layout
__device__ __align__(16) float d_cat[(size_t)B_*512*NP];      // x1..x4 stacked [B,512,N]
__device__ __align__(16) float d_mx[(size_t)B_*NP*256];       // pre-BN max over k
__device__ __align__(16) float d_AT[(size_t)B_*NP*512];       // [bn][2O]: A then T
__device__ __align__(16) float d_WG[512*128];                 // [Wn; Wd] rows
__device__ __align__(16) float d_Y[(size_t)B_*1024*NP];       // final conv out
__device__ float d_sum[1024];
__device__ float d_sq[1024];
__device__ float d_scale[1024];
__device__ float d_shift[1024];

// ---- packed f32x2 helpers (FFMA2 path) ----
__device__ __forceinline__ unsigned long long pk2(float lo, float hi) {
    unsigned long long r;
    asm("mov.b64 %0, {%1, %2};" : "=l"(r) : "f"(lo), "f"(hi));
    return r;
}
__device__ __forceinline__ float2 upk2(unsigned long long v) {
    float lo, hi;
    asm("mov.b64 {%0, %1}, %2;" : "=f"(lo), "=f"(hi) : "l"(v));
    return make_float2(lo, hi);
}
__device__ __forceinline__ unsigned long long fma2(unsigned long long a,
                                                   unsigned long long b,
                                                   unsigned long long c) {
    unsigned long long d;
    asm("fma.rn.f32x2 %0, %1, %2, %3;" : "=l"(d) : "l"(a), "l"(b), "l"(c));
    return d;
}

__device__ __forceinline__ const float* layer_src(const float* ext, int coff, int b, int bstride) {
    if (ext) return ext + (size_t)b * bstride;
    return d_cat + (size_t)b * 512 * NP + (size_t)coff * NP;
}

// ---- 8x8 FFMA2 microkernel step over a 16-deep smem tile (frozen R5/R10 form) ----
__device__ __forceinline__ void mk_step(const float* As, const float* Bs,
                                        int aoff, int boff,
                                        unsigned long long (&acc)[8][4]) {
    #pragma unroll
    for (int kk=0; kk<16; kk++) {
        const float* ar = As + kk*128 + aoff;
        const float* br = Bs + kk*128 + boff;
        float4 a0 = *(const float4*)ar;
        float4 a1 = *(const float4*)(ar+4);
        float4 b0 = *(const float4*)br;
        float4 b1 = *(const float4*)(br+4);
        unsigned long long bp[4] = {pk2(b0.x,b0.y), pk2(b0.z,b0.w),
                                    pk2(b1.x,b1.y), pk2(b1.z,b1.w)};
        float av[8] = {a0.x,a0.y,a0.z,a0.w,a1.x,a1.y,a1.z,a1.w};
        #pragma unroll
        for (int i=0;i<8;i++) {
            unsigned long long ad = pk2(av[i], av[i]);
            #pragma unroll
            for (int jp=0;jp<4;jp++) acc[i][jp] = fma2(ad, bp[jp], acc[i][jp]);
        }
    }
}

// ---- radix scan helper: pick bin v s.t. count(>v) < need <= count(>=v) ----
__device__ __forceinline__ void radix_scan(const unsigned* hist, unsigned need,
                                           unsigned* sh_v, unsigned* sh_need2) {
    int tid = threadIdx.x;
    if (tid < 32) {
        unsigned base = tid*8;
        unsigned suf[8]; unsigned s = 0;
        #pragma unroll
        for (int j=7;j>=0;j--){ s += hist[base+j]; suf[j] = s; }
        unsigned incl = s;
        #pragma unroll
        for (int d=1; d<32; d<<=1) {
            unsigned o = __shfl_down_sync(0xffffffffu, incl, d);
            if (tid + d < 32) incl += o;
        }
        unsigned lane_above = incl - s;
        #pragma unroll
        for (int j=0;j<8;j++) {
            unsigned cg  = lane_above + suf[j];
            unsigned cgt = cg - hist[base+j];
            if (cgt < need && need <= cg) { *sh_v = base + j; *sh_need2 = need - cgt; }
        }
    }
}

// ---- transpose src slice [C,NP] -> d_xT [NP,C] (layer 1 only) ----
__global__ void k_transpose(const float* ext, int coff, int bstride, int C) {
    int b = blockIdx.z;
    const float* S = layer_src(ext, coff, b, bstride);
    __shared__ float tile[32][33];
    int n0 = blockIdx.x*32, c0 = blockIdx.y*32;
    #pragma unroll
    for (int q=0;q<4;q++) {
        int c = c0 + threadIdx.y + q*8;
        if (c < C) tile[threadIdx.y + q*8][threadIdx.x] = S[(size_t)c*NP + n0 + threadIdx.x];
    }
    __syncthreads();
    #pragma unroll
    for (int q=0;q<4;q++) {
        int n = n0 + threadIdx.y + q*8;
        int c = c0 + threadIdx.x;
        if (c < C) d_xT[((size_t)b*NP + n)*C + c] = tile[threadIdx.x][threadIdx.y + q*8];
    }
}

// ---- squared norms per point ----
__global__ void k_norms(const float* ext, int coff, int bstride, int C) {
    int b = blockIdx.y;
    int n = blockIdx.x*256 + threadIdx.x;
    const float* S = layer_src(ext, coff, b, bstride);
    float s = 0.f;
    for (int c=0;c<C;c++){ float v = S[(size_t)c*NP + n]; s += v*v; }
    d_xx[b*NP + n] = s;
}

// ---- layer-1 gram (C=3, old 64x64 path); b = bbase + blockIdx.z ----
__global__ void k_gram(const float* ext, int coff, int bstride, int C, int bbase) {
    int b = bbase + blockIdx.z;
    const float* S = layer_src(ext, coff, b, bstride);
    int n0 = blockIdx.y*64, m0 = blockIdx.x*64;
    __shared__ __align__(16) float As[16][64];
    __shared__ __align__(16) float Bs[16][64];
    int tid = threadIdx.x;
    int tx = tid & 15, ty = tid >> 4;
    int lr = tid >> 4;
    int lc = (tid & 15) * 4;
    unsigned long long acc2[4][2] = {};
    for (int c0=0;c0<C;c0+=16) {
        float4 av, bv;
        if (c0 + lr < C) {
            av = *(const float4*)&S[(size_t)(c0+lr)*NP + n0 + lc];
            bv = *(const float4*)&S[(size_t)(c0+lr)*NP + m0 + lc];
        } else { av = make_float4(0.f,0.f,0.f,0.f); bv = av; }
        *(float4*)&As[lr][lc] = av;
        *(float4*)&Bs[lr][lc] = bv;
        __syncthreads();
        #pragma unroll
        for (int kk=0;kk<16;kk++) {
            float4 a  = *(float4*)&As[kk][ty*4];
            float4 bq = *(float4*)&Bs[kk][tx*4];
            unsigned long long bp0 = pk2(bq.x, bq.y);
            unsigned long long bp1 = pk2(bq.z, bq.w);
            float ar[4] = {a.x,a.y,a.z,a.w};
            #pragma unroll
            for (int i=0;i<4;i++) {
                unsigned long long ad = pk2(ar[i], ar[i]);
                acc2[i][0] = fma2(ad, bp0, acc2[i][0]);
                acc2[i][1] = fma2(ad, bp1, acc2[i][1]);
            }
        }
        __syncthreads();
    }
    float xn[4], xm[4];
    #pragma unroll
    for (int i=0;i<4;i++) xn[i] = d_xx[b*NP + n0 + ty*4 + i];
    #pragma unroll
    for (int j=0;j<4;j++) xm[j] = d_xx[b*NP + m0 + tx*4 + j];
    #pragma unroll
    for (int i=0;i<4;i++) {
        float2 u0 = upk2(acc2[i][0]);
        float2 u1 = upk2(acc2[i][1]);
        float4 w;
        w.x = 2.f*u0.x - xn[i] - xm[0];
        w.y = 2.f*u0.y - xn[i] - xm[1];
        w.z = 2.f*u1.x - xn[i] - xm[2];
        w.w = 2.f*u1.y - xn[i] - xm[3];
        *(float4*)&d_D[((size_t)b*NP + n0+ty*4+i)*NP + m0+tx*4] = w;
    }
}

// ---- SYMMETRIC gram 128x128 / 8x8 FFMA2 (layers 2-4); b = bbase + blockIdx.z ----
template<int C>
__global__ __launch_bounds__(256) void k_gram2s(int coff, int bbase) {
    int bi = blockIdx.y, bj = blockIdx.x;
    if (bj < bi) return;
    int b = bbase + blockIdx.z;
    const float* S = d_cat + (size_t)b*512*NP + (size_t)coff*NP;
    int n0 = bi*128, m0 = bj*128;
    extern __shared__ float sm[];
    float* As = sm;
    float* Bs = sm + 16*128;
    int tid = threadIdx.x;
    int lrow = tid >> 4, lcol = (tid & 15) * 8;
    int lane = tid & 31, w = tid >> 5;
    int aoff = (w & 3)*32 + (lane >> 3)*8;
    int boff = (w >> 2)*64 + (lane & 7)*8;
    unsigned long long acc[8][4] = {};
    for (int c0=0;c0<C;c0+=16) {
        const float* Sr = S + (size_t)(c0+lrow)*NP;
        *(float4*)&As[lrow*128+lcol]   = *(const float4*)&Sr[n0+lcol];
        *(float4*)&As[lrow*128+lcol+4] = *(const float4*)&Sr[n0+lcol+4];
        *(float4*)&Bs[lrow*128+lcol]   = *(const float4*)&Sr[m0+lcol];
        *(float4*)&Bs[lrow*128+lcol+4] = *(const float4*)&Sr[m0+lcol+4];
        __syncthreads();
        mk_step(As, Bs, aoff, boff, acc);
        __syncthreads();
    }
    float xm[8];
    #pragma unroll
    for (int j=0;j<8;j++) xm[j] = d_xx[b*NP + m0 + boff + j];
    float wv[8][8];
    #pragma unroll
    for (int i=0;i<8;i++) {
        float xn = d_xx[b*NP + n0 + aoff + i];
        float2 u0 = upk2(acc[i][0]);
        float2 u1 = upk2(acc[i][1]);
        float2 u2 = upk2(acc[i][2]);
        float2 u3 = upk2(acc[i][3]);
        wv[i][0] = 2.f*u0.x - xn - xm[0];
        wv[i][1] = 2.f*u0.y - xn - xm[1];
        wv[i][2] = 2.f*u1.x - xn - xm[2];
        wv[i][3] = 2.f*u1.y - xn - xm[3];
        wv[i][4] = 2.f*u2.x - xn - xm[4];
        wv[i][5] = 2.f*u2.y - xn - xm[5];
        wv[i][6] = 2.f*u3.x - xn - xm[6];
        wv[i][7] = 2.f*u3.y - xn - xm[7];
        float* dst = &d_D[((size_t)b*NP + n0 + aoff + i)*NP + m0 + boff];
        *(float4*)dst     = make_float4(wv[i][0],wv[i][1],wv[i][2],wv[i][3]);
        *(float4*)(dst+4) = make_float4(wv[i][4],wv[i][5],wv[i][6],wv[i][7]);
    }
    if (bj > bi) {
        float* stage = sm;
        #pragma unroll 1
        for (int h = 0; h < 2; h++) {
            __syncthreads();
            if ((w >> 2) == h) {
                int cl = boff - h*64;
                #pragma unroll
                for (int jc=0;jc<8;jc++) {
                    #pragma unroll
                    for (int i=0;i<8;i++)
                        stage[(cl+jc)*129 + aoff + i] = wv[i][jc];
                }
            }
            __syncthreads();
            for (int e = tid; e < 64*32; e += 256) {
                int row = e >> 5;
                int c4  = (e & 31) * 4;
                const float* sp = stage + row*129 + c4;
                float4 v = make_float4(sp[0], sp[1], sp[2], sp[3]);
                *(float4*)&d_D[((size_t)b*NP + m0 + h*64 + row)*NP + n0 + c4] = v;
            }
        }
    }
}

// ---- top-20 SET per row: radix select with list compaction (R13 form); bn = bnoff + blockIdx.x ----
__global__ void k_select(int bnoff) {
    int bn = bnoff + blockIdx.x;
    __shared__ unsigned hist[256];
    __shared__ unsigned long long listA[NP];
    __shared__ unsigned long long listB[NP];
    __shared__ unsigned sh_v, sh_need2, sh_out, sh_cnt, sh_ecnt;
    const float* row = d_D + (size_t)bn*NP;
    int tid = threadIdx.x;  // 256
    unsigned key[8];
    hist[tid] = 0;
    if (tid == 0) { sh_out = 0; sh_cnt = 0; sh_ecnt = 0; }
    __syncthreads();
    #pragma unroll
    for (int q=0;q<8;q++) {
        unsigned fb = __float_as_uint(row[tid + q*256]);
        key[q] = (fb & 0x80000000u) ? ~fb : (fb | 0x80000000u);
        atomicAdd(&hist[key[q] >> 24], 1u);
    }
    __syncthreads();
    radix_scan(hist, KNN, &sh_v, &sh_need2);
    __syncthreads();
    unsigned v = sh_v;
    unsigned need = sh_need2;
    #pragma unroll
    for (int q=0;q<8;q++) {
        unsigned b8 = key[q] >> 24;
        int m = tid + q*256;
        if (b8 > v) {
            unsigned slot = atomicAdd(&sh_out, 1u);
            d_idx[bn*KNN + slot] = m;
        } else if (b8 == v) {
            unsigned l = atomicAdd(&sh_cnt, 1u);
            listA[l] = ((unsigned long long)key[q] << 32) | (unsigned)m;
        }
    }
    __syncthreads();
    unsigned cnt = sh_cnt;
    unsigned long long* cur = listA;
    unsigned long long* nxt = listB;
    for (int shift = 16; shift >= 0; shift -= 8) {
        if (need == cnt) {
            for (unsigned j = tid; j < cnt; j += 256) {
                unsigned slot = atomicAdd(&sh_out, 1u);
                d_idx[bn*KNN + slot] = (int)(cur[j] & 0xffffffffull);
            }
            return;
        }
        hist[tid] = 0;
        __syncthreads();
        for (unsigned j = tid; j < cnt; j += 256)
            atomicAdd(&hist[(unsigned)(cur[j] >> (32+shift)) & 255u], 1u);
        __syncthreads();
        radix_scan(hist, need, &sh_v, &sh_need2);
        if (tid == 0) sh_cnt = 0;
        __syncthreads();
        v = sh_v;
        unsigned nd2 = sh_need2;
        for (unsigned j = tid; j < cnt; j += 256) {
            unsigned long long e = cur[j];
            unsigned b8 = (unsigned)(e >> (32+shift)) & 255u;
            if (b8 > v) {
                unsigned slot = atomicAdd(&sh_out, 1u);
                d_idx[bn*KNN + slot] = (int)(e & 0xffffffffull);
            } else if (b8 == v) {
                unsigned l = atomicAdd(&sh_cnt, 1u);
                nxt[l] = e;
            }
        }
        __syncthreads();
        cnt = sh_cnt; need = nd2;
        unsigned long long* t = cur; cur = nxt; nxt = t;
    }
    for (unsigned j = tid; j < cnt; j += 256) {
        unsigned e2 = atomicAdd(&sh_ecnt, 1u);
        if (e2 < need) {
            unsigned slot = atomicAdd(&sh_out, 1u);
            d_idx[bn*KNN + slot] = (int)(cur[j] & 0xffffffffull);
        }
    }
}

__global__ void k_zero() {
    int i = blockIdx.x*blockDim.x + threadIdx.x;
    if (i < 1024) { d_sum[i]=0.f; d_sq[i]=0.f; }
}

// ---- legacy edge conv for layer 1 (C=3 — tiny) ----
template<int C, int O>
__global__ void k_edgeconv(const float* __restrict__ W) {
    int bn = blockIdx.x;
    int b = bn >> 11;
    int n = bn & (NP-1);
    constexpr int CP = (C < 4) ? 4 : C;
    __shared__ __align__(16) float s_ctr[CP];
    __shared__ __align__(16) float s_nbr[KNN*CP];
    __shared__ int s_idx[KNN];
    int tid = threadIdx.x;
    int TH = blockDim.x;
    if (tid < KNN) s_idx[tid] = d_idx[bn*KNN + tid];
    const float* xb = d_xT + (size_t)b*NP*C;
    for (int c=tid;c<C;c+=TH) s_ctr[c] = xb[(size_t)n*C + c];
    __syncthreads();
    for (int e=tid;e<KNN*C;e+=TH) {
        int j = e / C, c = e - j*C;
        s_nbr[j*CP + c] = xb[(size_t)s_idx[j]*C + c];
    }
    __syncthreads();
    for (int o=tid;o<O;o+=TH) {
        const float* Wo = W + o*2*C;
        float t = 0.f;
        for (int c=0;c<C;c++) t += (Wo[C+c] - Wo[c]) * s_ctr[c];
        float y[KNN];
        #pragma unroll
        for (int k=0;k<KNN;k++) y[k] = t;
        for (int c=0;c<C;c++) {
            float w = Wo[c];
            #pragma unroll
            for (int k=0;k<KNN;k++) y[k] += w * s_nbr[k*CP + c];
        }
        float mx = -1e30f, s = 0.f, sq = 0.f;
        #pragma unroll
        for (int k=0;k<KNN;k++) {
            mx = fmaxf(mx, y[k]);
            s += y[k];
            sq += y[k]*y[k];
        }
        d_mx[(size_t)bn*O + o] = mx;
        atomicAdd(&d_sum[o], s);
        atomicAdd(&d_sq[o], sq);
    }
}

// ---- build combined weights: rows [0,O) = Wn, rows [O,2O) = W2 - Wn ----
__global__ void k_wprep(const float* __restrict__ W, int O, int C) {
    int i = blockIdx.x*256 + threadIdx.x;
    if (i >= 2*O*C) return;
    int o = i / C, c = i - o*C;
    if (o < O) d_WG[i] = W[(size_t)o*2*C + c];
    else {
        int oo = o - O;
        d_WG[i] = W[(size_t)oo*2*C + C + c] - W[(size_t)oo*2*C + c];
    }
}

// ---- AT GEMM 128x128 / 8x8 (frozen R10 form) ----
template<int C, int TWO_O>
__global__ __launch_bounds__(256) void k_atgemm2(int coff) {
    int b = blockIdx.z;
    int o0 = blockIdx.y*128, n0 = blockIdx.x*128;
    const float* src = d_cat + (size_t)b*512*NP + (size_t)coff*NP;
    __shared__ __align__(16) float As[16*128];
    __shared__ __align__(16) float Bs[16*128];
    int tid = threadIdx.x;
    int lrow = tid >> 4, lcol = (tid & 15) * 8;
    int o_l = tid >> 1, kh = (tid & 1) * 8;
    int lane = tid & 31, w = tid >> 5;
    int aoff = (w & 3)*32 + (lane >> 3)*8;
    int boff = (w >> 2)*64 + (lane & 7)*8;
    unsigned long long acc[8][4] = {};
    for (int c0=0;c0<C;c0+=16) {
        float4 w0 = *(const float4*)&d_WG[(size_t)(o0+o_l)*C + c0 + kh];
        float4 w1 = *(const float4*)&d_WG[(size_t)(o0+o_l)*C + c0 + kh + 4];
        As[(kh+0)*128+o_l]=w0.x; As[(kh+1)*128+o_l]=w0.y;
        As[(kh+2)*128+o_l]=w0.z; As[(kh+3)*128+o_l]=w0.w;
        As[(kh+4)*128+o_l]=w1.x; As[(kh+5)*128+o_l]=w1.y;
        As[(kh+6)*128+o_l]=w1.z; As[(kh+7)*128+o_l]=w1.w;
        const float* Sr = src + (size_t)(c0+lrow)*NP;
        *(float4*)&Bs[lrow*128+lcol]   = *(const float4*)&Sr[n0+lcol];
        *(float4*)&Bs[lrow*128+lcol+4] = *(const float4*)&Sr[n0+lcol+4];
        __syncthreads();
        mk_step(As, Bs, aoff, boff, acc);
        __syncthreads();
    }
    float u[8][8];
    #pragma unroll
    for (int i=0;i<8;i++) {
        #pragma unroll
        for (int jp=0;jp<4;jp++) {
            float2 p = upk2(acc[i][jp]);
            u[i][jp*2] = p.x; u[i][jp*2+1] = p.y;
        }
    }
    #pragma unroll
    for (int j=0;j<8;j++) {
        float* dst = &d_AT[((size_t)b*NP + n0 + boff + j)*TWO_O + o0 + aoff];
        *(float4*)dst     = make_float4(u[0][j],u[1][j],u[2][j],u[3][j]);
        *(float4*)(dst+4) = make_float4(u[4][j],u[5][j],u[6][j],u[7][j]);
    }
}

// ---- gather + reduce: mx/sum/sq over 20 neighbors using A table ----
template<int O>
__global__ void k_gather() {
    constexpr int P = 16;
    constexpr int NPG = 256 / O;
    __shared__ int s_ix[P*KNN];
    int tid = threadIdx.x;
    int bn0 = blockIdx.x * P;
    for (int e = tid; e < P*KNN; e += 256) s_ix[e] = d_idx[bn0*KNN + e];
    __syncthreads();
    int pg = tid / O;
    int ol = tid - pg*O;
    float accS = 0.f, accQ = 0.f;
    for (int p = pg; p < P; p += NPG) {
        int bn = bn0 + p;
        int b = bn >> 11;
        size_t jbase = (size_t)b * NP;
        const int* ix = s_ix + p*KNN;
        float m = -3.4e38f, s = 0.f, q = 0.f;
        #pragma unroll
        for (int k=0;k<KNN;k++) {
            float v = d_AT[(jbase + ix[k])*(size_t)(2*O) + ol];
            m = fmaxf(m, v);
            s += v;
            q = fmaf(v, v, q);
        }
        float t = d_AT[(size_t)bn*(2*O) + O + ol];
        d_mx[(size_t)bn*O + ol] = m + t;
        accS += s + 20.f*t;
        accQ += q + 2.f*t*s + 20.f*t*t;
    }
    atomicAdd(&d_sum[ol], accS);
    atomicAdd(&d_sq [ol], accQ);
}

// ---- BN stats -> affine scale/shift per channel ----
__global__ void k_finalize(const float* __restrict__ g, const float* __restrict__ bb,
                           float inv, int O) {
    int o = blockIdx.x*blockDim.x + threadIdx.x;
    if (o >= O) return;
    float mean = d_sum[o]*inv;
    float var  = d_sq[o]*inv - mean*mean;
    float sc = g[o] / sqrtf(var + 1e-5f);
    d_scale[o] = sc;
    d_shift[o] = bb[o] - mean*sc;
}

// ---- apply BN+leaky to max_k and transpose into d_cat slice ----
__global__ void k_apply(int O, int coff) {
    int b = blockIdx.z;
    int n0 = blockIdx.x*32, o0 = blockIdx.y*32;
    __shared__ float tile[32][33];
    #pragma unroll
    for (int q=0;q<4;q++) {
        int n = n0 + threadIdx.y + q*8;
        int o = o0 + threadIdx.x;
        float v = d_mx[((size_t)b*NP + n)*O + o];
        float z = v*d_scale[o] + d_shift[o];
        z = (z > 0.f) ? z : 0.2f*z;
        tile[threadIdx.x][threadIdx.y + q*8] = z;
    }
    __syncthreads();
    #pragma unroll
    for (int q=0;q<4;q++) {
        int o = o0 + threadIdx.y + q*8;
        int n = n0 + threadIdx.x;
        d_cat[((size_t)b*512 + coff + o)*NP + n] = tile[threadIdx.y + q*8][threadIdx.x];
    }
}

// ---- final 512->1024 conv 128x128 / 8x8 with channel stats (frozen R10 form) ----
__global__ __launch_bounds__(256) void k_fgemm2(const float* __restrict__ W5) {
    int b = blockIdx.z;
    int o0 = blockIdx.y*128, n0 = blockIdx.x*128;
    const float* catb = d_cat + (size_t)b*512*NP;
    __shared__ __align__(16) float As[16*128];
    __shared__ __align__(16) float Bs[16*128];
    int tid = threadIdx.x;
    int lrow = tid >> 4, lcol = (tid & 15) * 8;
    int o_l = tid >> 1, kh = (tid & 1) * 8;
    int lane = tid & 31, w = tid >> 5;
    int aoff = (w & 3)*32 + (lane >> 3)*8;
    int boff = (w >> 2)*64 + (lane & 7)*8;
    int ln = lane & 7;
    unsigned long long acc[8][4] = {};
    for (int c0=0;c0<512;c0+=16) {
        float4 w0 = *(const float4*)&W5[(size_t)(o0+o_l)*512 + c0 + kh];
        float4 w1 = *(const float4*)&W5[(size_t)(o0+o_l)*512 + c0 + kh + 4];
        As[(kh+0)*128+o_l]=w0.x; As[(kh+1)*128+o_l]=w0.y;
        As[(kh+2)*128+o_l]=w0.z; As[(kh+3)*128+o_l]=w0.w;
        As[(kh+4)*128+o_l]=w1.x; As[(kh+5)*128+o_l]=w1.y;
        As[(kh+6)*128+o_l]=w1.z; As[(kh+7)*128+o_l]=w1.w;
        const float* Sr = catb + (size_t)(c0+lrow)*NP;
        *(float4*)&Bs[lrow*128+lcol]   = *(const float4*)&Sr[n0+lcol];
        *(float4*)&Bs[lrow*128+lcol+4] = *(const float4*)&Sr[n0+lcol+4];
        __syncthreads();
        mk_step(As, Bs, aoff, boff, acc);
        __syncthreads();
    }
    float s8[8], q8[8];
    #pragma unroll
    for (int i=0;i<8;i++) {
        float2 u0 = upk2(acc[i][0]);
        float2 u1 = upk2(acc[i][1]);
        float2 u2 = upk2(acc[i][2]);
        float2 u3 = upk2(acc[i][3]);
        float vj[8] = {u0.x,u0.y,u1.x,u1.y,u2.x,u2.y,u3.x,u3.y};
        float* dst = &d_Y[((size_t)b*1024 + o0 + aoff + i)*NP + n0 + boff];
        *(float4*)dst     = make_float4(vj[0],vj[1],vj[2],vj[3]);
        *(float4*)(dst+4) = make_float4(vj[4],vj[5],vj[6],vj[7]);
        float s = 0.f, q = 0.f;
        #pragma unroll
        for (int j=0;j<8;j++) { s += vj[j]; q = fmaf(vj[j], vj[j], q); }
        s8[i] = s; q8[i] = q;
    }
    #pragma unroll
    for (int i=0;i<8;i++) {
        #pragma unroll
        for (int off=4;off;off>>=1) {
            s8[i] += __shfl_down_sync(0xffffffffu, s8[i], off, 8);
            q8[i] += __shfl_down_sync(0xffffffffu, q8[i], off, 8);
        }
    }
    if (ln == 0) {
        #pragma unroll
        for (int i=0;i<8;i++) {
            atomicAdd(&d_sum[o0 + aoff + i], s8[i]);
            atomicAdd(&d_sq [o0 + aoff + i], q8[i]);
        }
    }
}

// ---- per (b,o): BN+leaky then max and mean over n ----
__global__ void k_freduce(float* __restrict__ out) {
    int bo = blockIdx.x;
    int b = bo >> 10, o = bo & 1023;
    const float* y = d_Y + (size_t)bo*NP;
    float sc = d_scale[o], sh = d_shift[o];
    int tid = threadIdx.x;
    float mx = -1e30f, s = 0.f;
    #pragma unroll
    for (int q=0;q<8;q++) {
        float z = y[tid + q*256]*sc + sh;
        z = (z > 0.f) ? z : 0.2f*z;
        mx = fmaxf(mx, z); s += z;
    }
    #pragma unroll
    for (int off=16;off;off>>=1) {
        mx = fmaxf(mx, __shfl_down_sync(0xffffffffu, mx, off));
        s += __shfl_down_sync(0xffffffffu, s, off);
    }
    __shared__ float smx[8], ssm[8];
    if ((tid&31)==0) { smx[tid>>5]=mx; ssm[tid>>5]=s; }
    __syncthreads();
    if (tid==0) {
        #pragma unroll
        for (int i=1;i<8;i++){ mx=fmaxf(mx,smx[i]); s+=ssm[i]; }
        out[(size_t)b*2048 + o] = mx;
        out[(size_t)b*2048 + 1024 + o] = s * (1.f/2048.f);
    }
}

// ------------------------------- host -------------------------------
#define GRAM_SMEM (64*129*4 + 256)

template<int C, int O>
static void run_edge4(int coff_in, const float* W, const float* g, const float* bb,
                      int coff_out) {
    dim3 tb(32,8);
    k_norms<<<dim3(NP/256, B_), 256>>>(nullptr, coff_in, 0, C);
    // interleave gram & select at 2-image granularity for L2 residency of d_D
    for (int bbase = 0; bbase < B_; bbase += 2) {
        k_gram2s<C><<<dim3(16, 16, 2), 256, GRAM_SMEM>>>(coff_in, bbase);
        k_select<<<2*NP, 256>>>(bbase*NP);
    }
    k_zero<<<4,256>>>();
    k_wprep<<<(2*O*C + 255)/256, 256>>>(W, O, C);
    k_atgemm2<C, 2*O><<<dim3(NP/128, 2*O/128, B_), 256>>>(coff_in);
    k_gather<O><<<B_*NP/16, 256>>>();
    k_finalize<<<(O+127)/128,128>>>(g, bb, 1.f/(float)(B_*NP*KNN), O);
    k_apply<<<dim3(NP/32, O/32, B_), tb>>>(O, coff_out);
}

extern "C" void kernel_launch(void* const* d_in, const int* in_sizes, int n_in,
                              void* d_out, int out_size) {
    (void)in_sizes; (void)n_in; (void)out_size;
    const float* x  = (const float*)d_in[0];
    const float* W1 = (const float*)d_in[1];
    const float* W2 = (const float*)d_in[2];
    const float* W3 = (const float*)d_in[3];
    const float* W4 = (const float*)d_in[4];
    const float* W5 = (const float*)d_in[5];
    const float* g1 = (const float*)d_in[6];  const float* b1 = (const float*)d_in[7];
    const float* g2 = (const float*)d_in[8];  const float* b2 = (const float*)d_in[9];
    const float* g3 = (const float*)d_in[10]; const float* b3 = (const float*)d_in[11];
    const float* g4 = (const float*)d_in[12]; const float* b4 = (const float*)d_in[13];
    const float* g5 = (const float*)d_in[14]; const float* b5 = (const float*)d_in[15];
    float* out = (float*)d_out;

    // ---- layer 1 (C=3): legacy tiny path, interleaved gram/select ----
    {
        dim3 tb(32,8);
        k_transpose<<<dim3(NP/32, 1, B_), tb>>>(x, 0, 3*NP, 3);
        k_norms<<<dim3(NP/256, B_), 256>>>(x, 0, 3*NP, 3);
        for (int bbase = 0; bbase < B_; bbase += 2) {
            k_gram<<<dim3(NP/64, NP/64, 2), 256>>>(x, 0, 3*NP, 3, bbase);
            k_select<<<2*NP, 256>>>(bbase*NP);
        }
        k_zero<<<4,256>>>();
        k_edgeconv<3,64><<<B_*NP, 64>>>(W1);
        k_finalize<<<1,128>>>(g1, b1, 1.f/(float)(B_*NP*KNN), 64);
        k_apply<<<dim3(NP/32, 2, B_), tb>>>(64, 0);
    }
    run_edge4<64,  64 >(0,   W2, g2, b2,  64);
    run_edge4<64,  128>(64,  W3, g3, b3, 128);
    run_edge4<128, 256>(128, W4, g4, b4, 256);

    k_zero<<<4,256>>>();
    k_fgemm2<<<dim3(NP/128, 1024/128, B_), 256>>>(W5);
    k_finalize<<<8,128>>>(g5, b5, 1.f/(float)(B_*NP), 1024);
    k_freduce<<<B_*1024, 256>>>(out);
}

// round 16
// speedup vs baseline: 1.0430x; 1.0430x over previous
#include <cuda_runtime.h>
#include <math.h>
#include <stdint.h>

#define NP  2048
#define B_  8
#define KNN 20

// ------------------- device scratch (allocation-free) -------------------
__device__ float d_xx[B_*NP];
__device__ float d_D[(size_t)B_*NP*NP];                       // 134 MB distances
__device__ int   d_idx[B_*NP*KNN];
__device__ __align__(16) float d_xT[(size_t)B_*NP*4];         // layer-1 gather layout
__device__ __align__(16) float d_cat[(size_t)B_*512*NP];      // x1..x4 stacked [B,512,N]
__device__ __align__(16) float d_mx[(size_t)B_*NP*256];       // pre-BN max over k
__device__ __align__(16) float d_AT[(size_t)B_*NP*512];       // [bn][2O]: A then T
__device__ __align__(16) float d_WG[512*128];                 // [Wn; Wd] rows
__device__ __align__(16) float d_Y[(size_t)B_*1024*NP];       // final conv out
__device__ float d_sum[1024];
__device__ float d_sq[1024];
__device__ float d_scale[1024];
__device__ float d_shift[1024];

// ---- packed f32x2 helpers (FFMA2 path) ----
__device__ __forceinline__ unsigned long long pk2(float lo, float hi) {
    unsigned long long r;
    asm("mov.b64 %0, {%1, %2};" : "=l"(r) : "f"(lo), "f"(hi));
    return r;
}
__device__ __forceinline__ float2 upk2(unsigned long long v) {
    float lo, hi;
    asm("mov.b64 {%0, %1}, %2;" : "=f"(lo), "=f"(hi) : "l"(v));
    return make_float2(lo, hi);
}
__device__ __forceinline__ unsigned long long fma2(unsigned long long a,
                                                   unsigned long long b,
                                                   unsigned long long c) {
    unsigned long long d;
    asm("fma.rn.f32x2 %0, %1, %2, %3;" : "=l"(d) : "l"(a), "l"(b), "l"(c));
    return d;
}

__device__ __forceinline__ const float* layer_src(const float* ext, int coff, int b, int bstride) {
    if (ext) return ext + (size_t)b * bstride;
    return d_cat + (size_t)b * 512 * NP + (size_t)coff * NP;
}

// ---- 8x8 FFMA2 microkernel step over a 16-deep smem tile (frozen R5/R10 form) ----
__device__ __forceinline__ void mk_step(const float* As, const float* Bs,
                                        int aoff, int boff,
                                        unsigned long long (&acc)[8][4]) {
    #pragma unroll
    for (int kk=0; kk<16; kk++) {
        const float* ar = As + kk*128 + aoff;
        const float* br = Bs + kk*128 + boff;
        float4 a0 = *(const float4*)ar;
        float4 a1 = *(const float4*)(ar+4);
        float4 b0 = *(const float4*)br;
        float4 b1 = *(const float4*)(br+4);
        unsigned long long bp[4] = {pk2(b0.x,b0.y), pk2(b0.z,b0.w),
                                    pk2(b1.x,b1.y), pk2(b1.z,b1.w)};
        float av[8] = {a0.x,a0.y,a0.z,a0.w,a1.x,a1.y,a1.z,a1.w};
        #pragma unroll
        for (int i=0;i<8;i++) {
            unsigned long long ad = pk2(av[i], av[i]);
            #pragma unroll
            for (int jp=0;jp<4;jp++) acc[i][jp] = fma2(ad, bp[jp], acc[i][jp]);
        }
    }
}

// ---- radix scan helper: pick bin v s.t. count(>v) < need <= count(>=v) ----
__device__ __forceinline__ void radix_scan(const unsigned* hist, unsigned need,
                                           unsigned* sh_v, unsigned* sh_need2) {
    int tid = threadIdx.x;
    if (tid < 32) {
        unsigned base = tid*8;
        unsigned suf[8]; unsigned s = 0;
        #pragma unroll
        for (int j=7;j>=0;j--){ s += hist[base+j]; suf[j] = s; }
        unsigned incl = s;
        #pragma unroll
        for (int d=1; d<32; d<<=1) {
            unsigned o = __shfl_down_sync(0xffffffffu, incl, d);
            if (tid + d < 32) incl += o;
        }
        unsigned lane_above = incl - s;
        #pragma unroll
        for (int j=0;j<8;j++) {
            unsigned cg  = lane_above + suf[j];
            unsigned cgt = cg - hist[base+j];
            if (cgt < need && need <= cg) { *sh_v = base + j; *sh_need2 = need - cgt; }
        }
    }
}

// ---- shared select core: given 8 register keys, emit top-20 index set ----
__device__ __forceinline__ void select_core(unsigned (&key)[8], int bn,
                                            unsigned* hist,
                                            unsigned long long* listA,
                                            unsigned long long* listB,
                                            unsigned* sh5) {
    int tid = threadIdx.x;
    unsigned &sh_v = sh5[0], &sh_need2 = sh5[1], &sh_out = sh5[2],
             &sh_cnt = sh5[3], &sh_ecnt = sh5[4];
    #pragma unroll
    for (int q=0;q<8;q++) atomicAdd(&hist[key[q] >> 24], 1u);
    __syncthreads();
    radix_scan(hist, KNN, &sh_v, &sh_need2);
    __syncthreads();
    unsigned v = sh_v;
    unsigned need = sh_need2;
    #pragma unroll
    for (int q=0;q<8;q++) {
        unsigned b8 = key[q] >> 24;
        int m = tid + q*256;
        if (b8 > v) {
            unsigned slot = atomicAdd(&sh_out, 1u);
            d_idx[bn*KNN + slot] = m;
        } else if (b8 == v) {
            unsigned l = atomicAdd(&sh_cnt, 1u);
            listA[l] = ((unsigned long long)key[q] << 32) | (unsigned)m;
        }
    }
    __syncthreads();
    unsigned cnt = sh_cnt;
    unsigned long long* cur = listA;
    unsigned long long* nxt = listB;
    for (int shift = 16; shift >= 0; shift -= 8) {
        if (need == cnt) {
            for (unsigned j = tid; j < cnt; j += 256) {
                unsigned slot = atomicAdd(&sh_out, 1u);
                d_idx[bn*KNN + slot] = (int)(cur[j] & 0xffffffffull);
            }
            return;
        }
        hist[tid] = 0;
        __syncthreads();
        for (unsigned j = tid; j < cnt; j += 256)
            atomicAdd(&hist[(unsigned)(cur[j] >> (32+shift)) & 255u], 1u);
        __syncthreads();
        radix_scan(hist, need, &sh_v, &sh_need2);
        if (tid == 0) sh_cnt = 0;
        __syncthreads();
        v = sh_v;
        unsigned nd2 = sh_need2;
        for (unsigned j = tid; j < cnt; j += 256) {
            unsigned long long e = cur[j];
            unsigned b8 = (unsigned)(e >> (32+shift)) & 255u;
            if (b8 > v) {
                unsigned slot = atomicAdd(&sh_out, 1u);
                d_idx[bn*KNN + slot] = (int)(e & 0xffffffffull);
            } else if (b8 == v) {
                unsigned l = atomicAdd(&sh_cnt, 1u);
                nxt[l] = e;
            }
        }
        __syncthreads();
        cnt = sh_cnt; need = nd2;
        unsigned long long* t = cur; cur = nxt; nxt = t;
    }
    for (unsigned j = tid; j < cnt; j += 256) {
        unsigned e2 = atomicAdd(&sh_ecnt, 1u);
        if (e2 < need) {
            unsigned slot = atomicAdd(&sh_out, 1u);
            d_idx[bn*KNN + slot] = (int)(cur[j] & 0xffffffffull);
        }
    }
}

// ---- transpose src slice [C,NP] -> d_xT [NP,C] (layer 1 only) ----
__global__ void k_transpose(const float* ext, int coff, int bstride, int C) {
    int b = blockIdx.z;
    const float* S = layer_src(ext, coff, b, bstride);
    __shared__ float tile[32][33];
    int n0 = blockIdx.x*32, c0 = blockIdx.y*32;
    #pragma unroll
    for (int q=0;q<4;q++) {
        int c = c0 + threadIdx.y + q*8;
        if (c < C) tile[threadIdx.y + q*8][threadIdx.x] = S[(size_t)c*NP + n0 + threadIdx.x];
    }
    __syncthreads();
    #pragma unroll
    for (int q=0;q<4;q++) {
        int n = n0 + threadIdx.y + q*8;
        int c = c0 + threadIdx.x;
        if (c < C) d_xT[((size_t)b*NP + n)*C + c] = tile[threadIdx.x][threadIdx.y + q*8];
    }
}

// ---- squared norms per point (layers 2-4) ----
__global__ void k_norms(int coff, int C) {
    int b = blockIdx.y;
    int n = blockIdx.x*256 + threadIdx.x;
    const float* S = d_cat + (size_t)b*512*NP + (size_t)coff*NP;
    float s = 0.f;
    for (int c=0;c<C;c++){ float v = S[(size_t)c*NP + n]; s += v*v; }
    d_xx[b*NP + n] = s;
}

// ---- SYMMETRIC gram 128x128 / 8x8 FFMA2 (layers 2-4) ----
template<int C>
__global__ __launch_bounds__(256) void k_gram2s(int coff) {
    int bi = blockIdx.y, bj = blockIdx.x;
    if (bj < bi) return;
    int b = blockIdx.z;
    const float* S = d_cat + (size_t)b*512*NP + (size_t)coff*NP;
    int n0 = bi*128, m0 = bj*128;
    extern __shared__ float sm[];
    float* As = sm;
    float* Bs = sm + 16*128;
    int tid = threadIdx.x;
    int lrow = tid >> 4, lcol = (tid & 15) * 8;
    int lane = tid & 31, w = tid >> 5;
    int aoff = (w & 3)*32 + (lane >> 3)*8;
    int boff = (w >> 2)*64 + (lane & 7)*8;
    unsigned long long acc[8][4] = {};
    for (int c0=0;c0<C;c0+=16) {
        const float* Sr = S + (size_t)(c0+lrow)*NP;
        *(float4*)&As[lrow*128+lcol]   = *(const float4*)&Sr[n0+lcol];
        *(float4*)&As[lrow*128+lcol+4] = *(const float4*)&Sr[n0+lcol+4];
        *(float4*)&Bs[lrow*128+lcol]   = *(const float4*)&Sr[m0+lcol];
        *(float4*)&Bs[lrow*128+lcol+4] = *(const float4*)&Sr[m0+lcol+4];
        __syncthreads();
        mk_step(As, Bs, aoff, boff, acc);
        __syncthreads();
    }
    float xm[8];
    #pragma unroll
    for (int j=0;j<8;j++) xm[j] = d_xx[b*NP + m0 + boff + j];
    float wv[8][8];
    #pragma unroll
    for (int i=0;i<8;i++) {
        float xn = d_xx[b*NP + n0 + aoff + i];
        float2 u0 = upk2(acc[i][0]);
        float2 u1 = upk2(acc[i][1]);
        float2 u2 = upk2(acc[i][2]);
        float2 u3 = upk2(acc[i][3]);
        wv[i][0] = 2.f*u0.x - xn - xm[0];
        wv[i][1] = 2.f*u0.y - xn - xm[1];
        wv[i][2] = 2.f*u1.x - xn - xm[2];
        wv[i][3] = 2.f*u1.y - xn - xm[3];
        wv[i][4] = 2.f*u2.x - xn - xm[4];
        wv[i][5] = 2.f*u2.y - xn - xm[5];
        wv[i][6] = 2.f*u3.x - xn - xm[6];
        wv[i][7] = 2.f*u3.y - xn - xm[7];
        float* dst = &d_D[((size_t)b*NP + n0 + aoff + i)*NP + m0 + boff];
        *(float4*)dst     = make_float4(wv[i][0],wv[i][1],wv[i][2],wv[i][3]);
        *(float4*)(dst+4) = make_float4(wv[i][4],wv[i][5],wv[i][6],wv[i][7]);
    }
    if (bj > bi) {
        float* stage = sm;
        #pragma unroll 1
        for (int h = 0; h < 2; h++) {
            __syncthreads();
            if ((w >> 2) == h) {
                int cl = boff - h*64;
                #pragma unroll
                for (int jc=0;jc<8;jc++) {
                    #pragma unroll
                    for (int i=0;i<8;i++)
                        stage[(cl+jc)*129 + aoff + i] = wv[i][jc];
                }
            }
            __syncthreads();
            for (int e = tid; e < 64*32; e += 256) {
                int row = e >> 5;
                int c4  = (e & 31) * 4;
                const float* sp = stage + row*129 + c4;
                float4 v = make_float4(sp[0], sp[1], sp[2], sp[3]);
                *(float4*)&d_D[((size_t)b*NP + m0 + h*64 + row)*NP + n0 + c4] = v;
            }
        }
    }
}

// ---- select from d_D (layers 2-4, R13 form) ----
__global__ void k_select() {
    int bn = blockIdx.x;
    __shared__ unsigned hist[256];
    __shared__ unsigned long long listA[NP];
    __shared__ unsigned long long listB[NP];
    __shared__ unsigned sh5[5];
    const float* row = d_D + (size_t)bn*NP;
    int tid = threadIdx.x;
    unsigned key[8];
    hist[tid] = 0;
    if (tid < 5) sh5[tid] = 0;
    __syncthreads();
    #pragma unroll
    for (int q=0;q<8;q++) {
        unsigned fb = __float_as_uint(row[tid + q*256]);
        key[q] = (fb & 0x80000000u) ? ~fb : (fb | 0x80000000u);
    }
    select_core(key, bn, hist, listA, listB, sh5);
}

// ---- layer-1 fused distance + select (C=3, no d_D) ----
__global__ void k_select1(const float* __restrict__ x) {
    int bn = blockIdx.x;
    int b = bn >> 11;
    int n = bn & (NP-1);
    __shared__ float sx[NP], sy[NP], sz[NP];
    __shared__ unsigned hist[256];
    __shared__ unsigned long long listA[NP];
    __shared__ unsigned long long listB[NP];
    __shared__ unsigned sh5[5];
    int tid = threadIdx.x;
    const float* xb = x + (size_t)b*3*NP;
    #pragma unroll
    for (int q=0;q<8;q++) {
        int m = tid + q*256;
        sx[m] = xb[m];
        sy[m] = xb[NP + m];
        sz[m] = xb[2*NP + m];
    }
    hist[tid] = 0;
    if (tid < 5) sh5[tid] = 0;
    __syncthreads();
    float xn = sx[n], yn = sy[n], zn = sz[n];
    float xxn = fmaf(zn, zn, fmaf(yn, yn, xn*xn));
    unsigned key[8];
    #pragma unroll
    for (int q=0;q<8;q++) {
        int m = tid + q*256;
        float xm = sx[m], ym = sy[m], zm = sz[m];
        float inner = fmaf(zn, zm, fmaf(yn, ym, xn*xm));
        float xxm = fmaf(zm, zm, fmaf(ym, ym, xm*xm));
        float dvv = 2.f*inner - xxn - xxm;
        unsigned fb = __float_as_uint(dvv);
        key[q] = (fb & 0x80000000u) ? ~fb : (fb | 0x80000000u);
    }
    select_core(key, bn, hist, listA, listB, sh5);
}

__global__ void k_zero() {
    int i = blockIdx.x*blockDim.x + threadIdx.x;
    if (i < 1024) { d_sum[i]=0.f; d_sq[i]=0.f; }
}

// ---- legacy edge conv for layer 1 (C=3 — tiny) ----
template<int C, int O>
__global__ void k_edgeconv(const float* __restrict__ W) {
    int bn = blockIdx.x;
    int b = bn >> 11;
    int n = bn & (NP-1);
    constexpr int CP = (C < 4) ? 4 : C;
    __shared__ __align__(16) float s_ctr[CP];
    __shared__ __align__(16) float s_nbr[KNN*CP];
    __shared__ int s_idx[KNN];
    int tid = threadIdx.x;
    int TH = blockDim.x;
    if (tid < KNN) s_idx[tid] = d_idx[bn*KNN + tid];
    const float* xb = d_xT + (size_t)b*NP*C;
    for (int c=tid;c<C;c+=TH) s_ctr[c] = xb[(size_t)n*C + c];
    __syncthreads();
    for (int e=tid;e<KNN*C;e+=TH) {
        int j = e / C, c = e - j*C;
        s_nbr[j*CP + c] = xb[(size_t)s_idx[j]*C + c];
    }
    __syncthreads();
    for (int o=tid;o<O;o+=TH) {
        const float* Wo = W + o*2*C;
        float t = 0.f;
        for (int c=0;c<C;c++) t += (Wo[C+c] - Wo[c]) * s_ctr[c];
        float y[KNN];
        #pragma unroll
        for (int k=0;k<KNN;k++) y[k] = t;
        for (int c=0;c<C;c++) {
            float w = Wo[c];
            #pragma unroll
            for (int k=0;k<KNN;k++) y[k] += w * s_nbr[k*CP + c];
        }
        float mx = -1e30f, s = 0.f, sq = 0.f;
        #pragma unroll
        for (int k=0;k<KNN;k++) {
            mx = fmaxf(mx, y[k]);
            s += y[k];
            sq += y[k]*y[k];
        }
        d_mx[(size_t)bn*O + o] = mx;
        atomicAdd(&d_sum[o], s);
        atomicAdd(&d_sq[o], sq);
    }
}

// ---- build combined weights: rows [0,O) = Wn, rows [O,2O) = W2 - Wn ----
__global__ void k_wprep(const float* __restrict__ W, int O, int C) {
    int i = blockIdx.x*256 + threadIdx.x;
    if (i >= 2*O*C) return;
    int o = i / C, c = i - o*C;
    if (o < O) d_WG[i] = W[(size_t)o*2*C + c];
    else {
        int oo = o - O;
        d_WG[i] = W[(size_t)oo*2*C + C + c] - W[(size_t)oo*2*C + c];
    }
}

// ---- AT GEMM 128x128 / 8x8 (frozen R10 form) ----
template<int C, int TWO_O>
__global__ __launch_bounds__(256) void k_atgemm2(int coff) {
    int b = blockIdx.z;
    int o0 = blockIdx.y*128, n0 = blockIdx.x*128;
    const float* src = d_cat + (size_t)b*512*NP + (size_t)coff*NP;
    __shared__ __align__(16) float As[16*128];
    __shared__ __align__(16) float Bs[16*128];
    int tid = threadIdx.x;
    int lrow = tid >> 4, lcol = (tid & 15) * 8;
    int o_l = tid >> 1, kh = (tid & 1) * 8;
    int lane = tid & 31, w = tid >> 5;
    int aoff = (w & 3)*32 + (lane >> 3)*8;
    int boff = (w >> 2)*64 + (lane & 7)*8;
    unsigned long long acc[8][4] = {};
    for (int c0=0;c0<C;c0+=16) {
        float4 w0 = *(const float4*)&d_WG[(size_t)(o0+o_l)*C + c0 + kh];
        float4 w1 = *(const float4*)&d_WG[(size_t)(o0+o_l)*C + c0 + kh + 4];
        As[(kh+0)*128+o_l]=w0.x; As[(kh+1)*128+o_l]=w0.y;
        As[(kh+2)*128+o_l]=w0.z; As[(kh+3)*128+o_l]=w0.w;
        As[(kh+4)*128+o_l]=w1.x; As[(kh+5)*128+o_l]=w1.y;
        As[(kh+6)*128+o_l]=w1.z; As[(kh+7)*128+o_l]=w1.w;
        const float* Sr = src + (size_t)(c0+lrow)*NP;
        *(float4*)&Bs[lrow*128+lcol]   = *(const float4*)&Sr[n0+lcol];
        *(float4*)&Bs[lrow*128+lcol+4] = *(const float4*)&Sr[n0+lcol+4];
        __syncthreads();
        mk_step(As, Bs, aoff, boff, acc);
        __syncthreads();
    }
    float u[8][8];
    #pragma unroll
    for (int i=0;i<8;i++) {
        #pragma unroll
        for (int jp=0;jp<4;jp++) {
            float2 p = upk2(acc[i][jp]);
            u[i][jp*2] = p.x; u[i][jp*2+1] = p.y;
        }
    }
    #pragma unroll
    for (int j=0;j<8;j++) {
        float* dst = &d_AT[((size_t)b*NP + n0 + boff + j)*TWO_O + o0 + aoff];
        *(float4*)dst     = make_float4(u[0][j],u[1][j],u[2][j],u[3][j]);
        *(float4*)(dst+4) = make_float4(u[4][j],u[5][j],u[6][j],u[7][j]);
    }
}

// ---- gather + reduce: mx/sum/sq over 20 neighbors using A table ----
template<int O>
__global__ void k_gather() {
    constexpr int P = 16;
    constexpr int NPG = 256 / O;
    __shared__ int s_ix[P*KNN];
    int tid = threadIdx.x;
    int bn0 = blockIdx.x * P;
    for (int e = tid; e < P*KNN; e += 256) s_ix[e] = d_idx[bn0*KNN + e];
    __syncthreads();
    int pg = tid / O;
    int ol = tid - pg*O;
    float accS = 0.f, accQ = 0.f;
    for (int p = pg; p < P; p += NPG) {
        int bn = bn0 + p;
        int b = bn >> 11;
        size_t jbase = (size_t)b * NP;
        const int* ix = s_ix + p*KNN;
        float m = -3.4e38f, s = 0.f, q = 0.f;
        #pragma unroll
        for (int k=0;k<KNN;k++) {
            float v = d_AT[(jbase + ix[k])*(size_t)(2*O) + ol];
            m = fmaxf(m, v);
            s += v;
            q = fmaf(v, v, q);
        }
        float t = d_AT[(size_t)bn*(2*O) + O + ol];
        d_mx[(size_t)bn*O + ol] = m + t;
        accS += s + 20.f*t;
        accQ += q + 2.f*t*s + 20.f*t*t;
    }
    atomicAdd(&d_sum[ol], accS);
    atomicAdd(&d_sq [ol], accQ);
}

// ---- BN stats -> affine scale/shift per channel ----
__global__ void k_finalize(const float* __restrict__ g, const float* __restrict__ bb,
                           float inv, int O) {
    int o = blockIdx.x*blockDim.x + threadIdx.x;
    if (o >= O) return;
    float mean = d_sum[o]*inv;
    float var  = d_sq[o]*inv - mean*mean;
    float sc = g[o] / sqrtf(var + 1e-5f);
    d_scale[o] = sc;
    d_shift[o] = bb[o] - mean*sc;
}

// ---- apply BN+leaky to max_k and transpose into d_cat slice ----
__global__ void k_apply(int O, int coff) {
    int b = blockIdx.z;
    int n0 = blockIdx.x*32, o0 = blockIdx.y*32;
    __shared__ float tile[32][33];
    #pragma unroll
    for (int q=0;q<4;q++) {
        int n = n0 + threadIdx.y + q*8;
        int o = o0 + threadIdx.x;
        float v = d_mx[((size_t)b*NP + n)*O + o];
        float z = v*d_scale[o] + d_shift[o];
        z = (z > 0.f) ? z : 0.2f*z;
        tile[threadIdx.x][threadIdx.y + q*8] = z;
    }
    __syncthreads();
    #pragma unroll
    for (int q=0;q<4;q++) {
        int o = o0 + threadIdx.y + q*8;
        int n = n0 + threadIdx.x;
        d_cat[((size_t)b*512 + coff + o)*NP + n] = tile[threadIdx.y + q*8][threadIdx.x];
    }
}

// ---- final 512->1024 conv 128x128 / 8x8 with channel stats (frozen R10 form) ----
__global__ __launch_bounds__(256) void k_fgemm2(const float* __restrict__ W5) {
    int b = blockIdx.z;
    int o0 = blockIdx.y*128, n0 = blockIdx.x*128;
    const float* catb = d_cat + (size_t)b*512*NP;
    __shared__ __align__(16) float As[16*128];
    __shared__ __align__(16) float Bs[16*128];
    int tid = threadIdx.x;
    int lrow = tid >> 4, lcol = (tid & 15) * 8;
    int o_l = tid >> 1, kh = (tid & 1) * 8;
    int lane = tid & 31, w = tid >> 5;
    int aoff = (w & 3)*32 + (lane >> 3)*8;
    int boff = (w >> 2)*64 + (lane & 7)*8;
    int ln = lane & 7;
    unsigned long long acc[8][4] = {};
    for (int c0=0;c0<512;c0+=16) {
        float4 w0 = *(const float4*)&W5[(size_t)(o0+o_l)*512 + c0 + kh];
        float4 w1 = *(const float4*)&W5[(size_t)(o0+o_l)*512 + c0 + kh + 4];
        As[(kh+0)*128+o_l]=w0.x; As[(kh+1)*128+o_l]=w0.y;
        As[(kh+2)*128+o_l]=w0.z; As[(kh+3)*128+o_l]=w0.w;
        As[(kh+4)*128+o_l]=w1.x; As[(kh+5)*128+o_l]=w1.y;
        As[(kh+6)*128+o_l]=w1.z; As[(kh+7)*128+o_l]=w1.w;
        const float* Sr = catb + (size_t)(c0+lrow)*NP;
        *(float4*)&Bs[lrow*128+lcol]   = *(const float4*)&Sr[n0+lcol];
        *(float4*)&Bs[lrow*128+lcol+4] = *(const float4*)&Sr[n0+lcol+4];
        __syncthreads();
        mk_step(As, Bs, aoff, boff, acc);
        __syncthreads();
    }
    float s8[8], q8[8];
    #pragma unroll
    for (int i=0;i<8;i++) {
        float2 u0 = upk2(acc[i][0]);
        float2 u1 = upk2(acc[i][1]);
        float2 u2 = upk2(acc[i][2]);
        float2 u3 = upk2(acc[i][3]);
        float vj[8] = {u0.x,u0.y,u1.x,u1.y,u2.x,u2.y,u3.x,u3.y};
        float* dst = &d_Y[((size_t)b*1024 + o0 + aoff + i)*NP + n0 + boff];
        *(float4*)dst     = make_float4(vj[0],vj[1],vj[2],vj[3]);
        *(float4*)(dst+4) = make_float4(vj[4],vj[5],vj[6],vj[7]);
        float s = 0.f, q = 0.f;
        #pragma unroll
        for (int j=0;j<8;j++) { s += vj[j]; q = fmaf(vj[j], vj[j], q); }
        s8[i] = s; q8[i] = q;
    }
    #pragma unroll
    for (int i=0;i<8;i++) {
        #pragma unroll
        for (int off=4;off;off>>=1) {
            s8[i] += __shfl_down_sync(0xffffffffu, s8[i], off, 8);
            q8[i] += __shfl_down_sync(0xffffffffu, q8[i], off, 8);
        }
    }
    if (ln == 0) {
        #pragma unroll
        for (int i=0;i<8;i++) {
            atomicAdd(&d_sum[o0 + aoff + i], s8[i]);
            atomicAdd(&d_sq [o0 + aoff + i], q8[i]);
        }
    }
}

// ---- per (b,o): BN+leaky then max and mean over n ----
__global__ void k_freduce(float* __restrict__ out) {
    int bo = blockIdx.x;
    int b = bo >> 10, o = bo & 1023;
    const float* y = d_Y + (size_t)bo*NP;
    float sc = d_scale[o], sh = d_shift[o];
    int tid = threadIdx.x;
    float mx = -1e30f, s = 0.f;
    #pragma unroll
    for (int q=0;q<8;q++) {
        float z = y[tid + q*256]*sc + sh;
        z = (z > 0.f) ? z : 0.2f*z;
        mx = fmaxf(mx, z); s += z;
    }
    #pragma unroll
    for (int off=16;off;off>>=1) {
        mx = fmaxf(mx, __shfl_down_sync(0xffffffffu, mx, off));
        s += __shfl_down_sync(0xffffffffu, s, off);
    }
    __shared__ float smx[8], ssm[8];
    if ((tid&31)==0) { smx[tid>>5]=mx; ssm[tid>>5]=s; }
    __syncthreads();
    if (tid==0) {
        #pragma unroll
        for (int i=1;i<8;i++){ mx=fmaxf(mx,smx[i]); s+=ssm[i]; }
        out[(size_t)b*2048 + o] = mx;
        out[(size_t)b*2048 + 1024 + o] = s * (1.f/2048.f);
    }
}

// ------------------------------- host -------------------------------
#define GRAM_SMEM (64*129*4 + 256)

template<int C, int O>
static void run_edge4(int coff_in, const float* W, const float* g, const float* bb,
                      int coff_out) {
    dim3 tb(32,8);
    k_norms<<<dim3(NP/256, B_), 256>>>(coff_in, C);
    k_gram2s<C><<<dim3(16, 16, B_), 256, GRAM_SMEM>>>(coff_in);
    k_select<<<B_*NP, 256>>>();
    k_zero<<<4,256>>>();
    k_wprep<<<(2*O*C + 255)/256, 256>>>(W, O, C);
    k_atgemm2<C, 2*O><<<dim3(NP/128, 2*O/128, B_), 256>>>(coff_in);
    k_gather<O><<<B_*NP/16, 256>>>();
    k_finalize<<<(O+127)/128,128>>>(g, bb, 1.f/(float)(B_*NP*KNN), O);
    k_apply<<<dim3(NP/32, O/32, B_), tb>>>(O, coff_out);
}

extern "C" void kernel_launch(void* const* d_in, const int* in_sizes, int n_in,
                              void* d_out, int out_size) {
    (void)in_sizes; (void)n_in; (void)out_size;
    const float* x  = (const float*)d_in[0];
    const float* W1 = (const float*)d_in[1];
    const float* W2 = (const float*)d_in[2];
    const float* W3 = (const float*)d_in[3];
    const float* W4 = (const float*)d_in[4];
    const float* W5 = (const float*)d_in[5];
    const float* g1 = (const float*)d_in[6];  const float* b1 = (const float*)d_in[7];
    const float* g2 = (const float*)d_in[8];  const float* b2 = (const float*)d_in[9];
    const float* g3 = (const float*)d_in[10]; const float* b3 = (const float*)d_in[11];
    const float* g4 = (const float*)d_in[12]; const float* b4 = (const float*)d_in[13];
    const float* g5 = (const float*)d_in[14]; const float* b5 = (const float*)d_in[15];
    float* out = (float*)d_out;

    // ---- layer 1 (C=3): fused distance+select (no d_D) ----
    {
        dim3 tb(32,8);
        k_transpose<<<dim3(NP/32, 1, B_), tb>>>(x, 0, 3*NP, 3);
        k_select1<<<B_*NP, 256>>>(x);
        k_zero<<<4,256>>>();
        k_edgeconv<3,64><<<B_*NP, 64>>>(W1);
        k_finalize<<<1,128>>>(g1, b1, 1.f/(float)(B_*NP*KNN), 64);
        k_apply<<<dim3(NP/32, 2, B_), tb>>>(64, 0);
    }
    run_edge4<64,  64 >(0,   W2, g2, b2,  64);
    run_edge4<64,  128>(64,  W3, g3, b3, 128);
    run_edge4<128, 256>(128, W4, g4, b4, 256);

    k_zero<<<4,256>>>();
    k_fgemm2<<<dim3(NP/128, 1024/128, B_), 256>>>(W5);
    k_finalize<<<8,128>>>(g5, b5, 1.f/(float)(B_*NP), 1024);
    k_freduce<<<B_*1024, 256>>>(out);
}

// round 17
// speedup vs baseline: 1.0781x; 1.0336x over previous
#include <cuda_runtime.h>
#include <math.h>
#include <stdint.h>

#define NP  2048
#define B_  8
#define KNN 20

// ------------------- device scratch (allocation-free) -------------------
__device__ float d_xx[B_*NP];
__device__ float d_D[(size_t)B_*NP*NP];                       // 134 MB distances
__device__ int   d_idx[B_*NP*KNN];
__device__ __align__(16) float d_x16[(size_t)B_*16*NP];       // layer-1 padded input
__device__ __align__(16) float d_cat[(size_t)B_*512*NP];      // x1..x4 stacked [B,512,N]
__device__ __align__(16) float d_mx[(size_t)B_*NP*256];       // pre-BN max over k
__device__ __align__(16) float d_AT[(size_t)B_*NP*512];       // [bn][2O]: A then T
__device__ __align__(16) float d_WG[512*128];                 // [Wn; Wd] rows
__device__ __align__(16) float d_Y[(size_t)B_*1024*NP];       // final conv out
__device__ float d_sum[1024];
__device__ float d_sq[1024];
__device__ float d_scale[1024];
__device__ float d_shift[1024];

// ---- packed f32x2 helpers (FFMA2 path) ----
__device__ __forceinline__ unsigned long long pk2(float lo, float hi) {
    unsigned long long r;
    asm("mov.b64 %0, {%1, %2};" : "=l"(r) : "f"(lo), "f"(hi));
    return r;
}
__device__ __forceinline__ float2 upk2(unsigned long long v) {
    float lo, hi;
    asm("mov.b64 {%0, %1}, %2;" : "=f"(lo), "=f"(hi) : "l"(v));
    return make_float2(lo, hi);
}
__device__ __forceinline__ unsigned long long fma2(unsigned long long a,
                                                   unsigned long long b,
                                                   unsigned long long c) {
    unsigned long long d;
    asm("fma.rn.f32x2 %0, %1, %2, %3;" : "=l"(d) : "l"(a), "l"(b), "l"(c));
    return d;
}

// ---- 8x8 FFMA2 microkernel step over a 16-deep smem tile (frozen R5/R10 form) ----
__device__ __forceinline__ void mk_step(const float* As, const float* Bs,
                                        int aoff, int boff,
                                        unsigned long long (&acc)[8][4]) {
    #pragma unroll
    for (int kk=0; kk<16; kk++) {
        const float* ar = As + kk*128 + aoff;
        const float* br = Bs + kk*128 + boff;
        float4 a0 = *(const float4*)ar;
        float4 a1 = *(const float4*)(ar+4);
        float4 b0 = *(const float4*)br;
        float4 b1 = *(const float4*)(br+4);
        unsigned long long bp[4] = {pk2(b0.x,b0.y), pk2(b0.z,b0.w),
                                    pk2(b1.x,b1.y), pk2(b1.z,b1.w)};
        float av[8] = {a0.x,a0.y,a0.z,a0.w,a1.x,a1.y,a1.z,a1.w};
        #pragma unroll
        for (int i=0;i<8;i++) {
            unsigned long long ad = pk2(av[i], av[i]);
            #pragma unroll
            for (int jp=0;jp<4;jp++) acc[i][jp] = fma2(ad, bp[jp], acc[i][jp]);
        }
    }
}

// ---- radix scan helper: pick bin v s.t. count(>v) < need <= count(>=v) ----
__device__ __forceinline__ void radix_scan(const unsigned* hist, unsigned need,
                                           unsigned* sh_v, unsigned* sh_need2) {
    int tid = threadIdx.x;
    if (tid < 32) {
        unsigned base = tid*8;
        unsigned suf[8]; unsigned s = 0;
        #pragma unroll
        for (int j=7;j>=0;j--){ s += hist[base+j]; suf[j] = s; }
        unsigned incl = s;
        #pragma unroll
        for (int d=1; d<32; d<<=1) {
            unsigned o = __shfl_down_sync(0xffffffffu, incl, d);
            if (tid + d < 32) incl += o;
        }
        unsigned lane_above = incl - s;
        #pragma unroll
        for (int j=0;j<8;j++) {
            unsigned cg  = lane_above + suf[j];
            unsigned cgt = cg - hist[base+j];
            if (cgt < need && need <= cg) { *sh_v = base + j; *sh_need2 = need - cgt; }
        }
    }
}

// ---- shared select core: given 8 register keys, emit top-20 index set ----
__device__ __forceinline__ void select_core(unsigned (&key)[8], int bn,
                                            unsigned* hist,
                                            unsigned long long* listA,
                                            unsigned long long* listB,
                                            unsigned* sh5) {
    int tid = threadIdx.x;
    unsigned &sh_v = sh5[0], &sh_need2 = sh5[1], &sh_out = sh5[2],
             &sh_cnt = sh5[3], &sh_ecnt = sh5[4];
    #pragma unroll
    for (int q=0;q<8;q++) atomicAdd(&hist[key[q] >> 24], 1u);
    __syncthreads();
    radix_scan(hist, KNN, &sh_v, &sh_need2);
    __syncthreads();
    unsigned v = sh_v;
    unsigned need = sh_need2;
    #pragma unroll
    for (int q=0;q<8;q++) {
        unsigned b8 = key[q] >> 24;
        int m = tid + q*256;
        if (b8 > v) {
            unsigned slot = atomicAdd(&sh_out, 1u);
            d_idx[bn*KNN + slot] = m;
        } else if (b8 == v) {
            unsigned l = atomicAdd(&sh_cnt, 1u);
            listA[l] = ((unsigned long long)key[q] << 32) | (unsigned)m;
        }
    }
    __syncthreads();
    unsigned cnt = sh_cnt;
    unsigned long long* cur = listA;
    unsigned long long* nxt = listB;
    for (int shift = 16; shift >= 0; shift -= 8) {
        if (need == cnt) {
            for (unsigned j = tid; j < cnt; j += 256) {
                unsigned slot = atomicAdd(&sh_out, 1u);
                d_idx[bn*KNN + slot] = (int)(cur[j] & 0xffffffffull);
            }
            return;
        }
        hist[tid] = 0;
        __syncthreads();
        for (unsigned j = tid; j < cnt; j += 256)
            atomicAdd(&hist[(unsigned)(cur[j] >> (32+shift)) & 255u], 1u);
        __syncthreads();
        radix_scan(hist, need, &sh_v, &sh_need2);
        if (tid == 0) sh_cnt = 0;
        __syncthreads();
        v = sh_v;
        unsigned nd2 = sh_need2;
        for (unsigned j = tid; j < cnt; j += 256) {
            unsigned long long e = cur[j];
            unsigned b8 = (unsigned)(e >> (32+shift)) & 255u;
            if (b8 > v) {
                unsigned slot = atomicAdd(&sh_out, 1u);
                d_idx[bn*KNN + slot] = (int)(e & 0xffffffffull);
            } else if (b8 == v) {
                unsigned l = atomicAdd(&sh_cnt, 1u);
                nxt[l] = e;
            }
        }
        __syncthreads();
        cnt = sh_cnt; need = nd2;
        unsigned long long* t = cur; cur = nxt; nxt = t;
    }
    for (unsigned j = tid; j < cnt; j += 256) {
        unsigned e2 = atomicAdd(&sh_ecnt, 1u);
        if (e2 < need) {
            unsigned slot = atomicAdd(&sh_out, 1u);
            d_idx[bn*KNN + slot] = (int)(cur[j] & 0xffffffffull);
        }
    }
}

// ---- squared norms per point (layers 2-4) ----
__global__ void k_norms(int coff, int C) {
    int b = blockIdx.y;
    int n = blockIdx.x*256 + threadIdx.x;
    const float* S = d_cat + (size_t)b*512*NP + (size_t)coff*NP;
    float s = 0.f;
    for (int c=0;c<C;c++){ float v = S[(size_t)c*NP + n]; s += v*v; }
    d_xx[b*NP + n] = s;
}

// ---- SYMMETRIC gram 128x128 / 8x8 FFMA2 (layers 2-4) ----
template<int C>
__global__ __launch_bounds__(256) void k_gram2s(int coff) {
    int bi = blockIdx.y, bj = blockIdx.x;
    if (bj < bi) return;
    int b = blockIdx.z;
    const float* S = d_cat + (size_t)b*512*NP + (size_t)coff*NP;
    int n0 = bi*128, m0 = bj*128;
    extern __shared__ float sm[];
    float* As = sm;
    float* Bs = sm + 16*128;
    int tid = threadIdx.x;
    int lrow = tid >> 4, lcol = (tid & 15) * 8;
    int lane = tid & 31, w = tid >> 5;
    int aoff = (w & 3)*32 + (lane >> 3)*8;
    int boff = (w >> 2)*64 + (lane & 7)*8;
    unsigned long long acc[8][4] = {};
    for (int c0=0;c0<C;c0+=16) {
        const float* Sr = S + (size_t)(c0+lrow)*NP;
        *(float4*)&As[lrow*128+lcol]   = *(const float4*)&Sr[n0+lcol];
        *(float4*)&As[lrow*128+lcol+4] = *(const float4*)&Sr[n0+lcol+4];
        *(float4*)&Bs[lrow*128+lcol]   = *(const float4*)&Sr[m0+lcol];
        *(float4*)&Bs[lrow*128+lcol+4] = *(const float4*)&Sr[m0+lcol+4];
        __syncthreads();
        mk_step(As, Bs, aoff, boff, acc);
        __syncthreads();
    }
    float xm[8];
    #pragma unroll
    for (int j=0;j<8;j++) xm[j] = d_xx[b*NP + m0 + boff + j];
    float wv[8][8];
    #pragma unroll
    for (int i=0;i<8;i++) {
        float xn = d_xx[b*NP + n0 + aoff + i];
        float2 u0 = upk2(acc[i][0]);
        float2 u1 = upk2(acc[i][1]);
        float2 u2 = upk2(acc[i][2]);
        float2 u3 = upk2(acc[i][3]);
        wv[i][0] = 2.f*u0.x - xn - xm[0];
        wv[i][1] = 2.f*u0.y - xn - xm[1];
        wv[i][2] = 2.f*u1.x - xn - xm[2];
        wv[i][3] = 2.f*u1.y - xn - xm[3];
        wv[i][4] = 2.f*u2.x - xn - xm[4];
        wv[i][5] = 2.f*u2.y - xn - xm[5];
        wv[i][6] = 2.f*u3.x - xn - xm[6];
        wv[i][7] = 2.f*u3.y - xn - xm[7];
        float* dst = &d_D[((size_t)b*NP + n0 + aoff + i)*NP + m0 + boff];
        *(float4*)dst     = make_float4(wv[i][0],wv[i][1],wv[i][2],wv[i][3]);
        *(float4*)(dst+4) = make_float4(wv[i][4],wv[i][5],wv[i][6],wv[i][7]);
    }
    if (bj > bi) {
        float* stage = sm;
        #pragma unroll 1
        for (int h = 0; h < 2; h++) {
            __syncthreads();
            if ((w >> 2) == h) {
                int cl = boff - h*64;
                #pragma unroll
                for (int jc=0;jc<8;jc++) {
                    #pragma unroll
                    for (int i=0;i<8;i++)
                        stage[(cl+jc)*129 + aoff + i] = wv[i][jc];
                }
            }
            __syncthreads();
            for (int e = tid; e < 64*32; e += 256) {
                int row = e >> 5;
                int c4  = (e & 31) * 4;
                const float* sp = stage + row*129 + c4;
                float4 v = make_float4(sp[0], sp[1], sp[2], sp[3]);
                *(float4*)&d_D[((size_t)b*NP + m0 + h*64 + row)*NP + n0 + c4] = v;
            }
        }
    }
}

// ---- select from d_D (layers 2-4, R13 form) ----
__global__ void k_select() {
    int bn = blockIdx.x;
    __shared__ unsigned hist[256];
    __shared__ unsigned long long listA[NP];
    __shared__ unsigned long long listB[NP];
    __shared__ unsigned sh5[5];
    const float* row = d_D + (size_t)bn*NP;
    int tid = threadIdx.x;
    unsigned key[8];
    hist[tid] = 0;
    if (tid < 5) sh5[tid] = 0;
    __syncthreads();
    #pragma unroll
    for (int q=0;q<8;q++) {
        unsigned fb = __float_as_uint(row[tid + q*256]);
        key[q] = (fb & 0x80000000u) ? ~fb : (fb | 0x80000000u);
    }
    select_core(key, bn, hist, listA, listB, sh5);
}

// ---- layer-1 fused distance + select (C=3, no d_D) ----
__global__ void k_select1(const float* __restrict__ x) {
    int bn = blockIdx.x;
    int b = bn >> 11;
    int n = bn & (NP-1);
    __shared__ float sx[NP], sy[NP], sz[NP];
    __shared__ unsigned hist[256];
    __shared__ unsigned long long listA[NP];
    __shared__ unsigned long long listB[NP];
    __shared__ unsigned sh5[5];
    int tid = threadIdx.x;
    const float* xb = x + (size_t)b*3*NP;
    #pragma unroll
    for (int q=0;q<8;q++) {
        int m = tid + q*256;
        sx[m] = xb[m];
        sy[m] = xb[NP + m];
        sz[m] = xb[2*NP + m];
    }
    hist[tid] = 0;
    if (tid < 5) sh5[tid] = 0;
    __syncthreads();
    float xn = sx[n], yn = sy[n], zn = sz[n];
    float xxn = fmaf(zn, zn, fmaf(yn, yn, xn*xn));
    unsigned key[8];
    #pragma unroll
    for (int q=0;q<8;q++) {
        int m = tid + q*256;
        float xm = sx[m], ym = sy[m], zm = sz[m];
        float inner = fmaf(zn, zm, fmaf(yn, ym, xn*xm));
        float xxm = fmaf(zm, zm, fmaf(ym, ym, xm*xm));
        float dvv = 2.f*inner - xxn - xxm;
        unsigned fb = __float_as_uint(dvv);
        key[q] = (fb & 0x80000000u) ? ~fb : (fb | 0x80000000u);
    }
    select_core(key, bn, hist, listA, listB, sh5);
}

__global__ void k_zero() {
    int i = blockIdx.x*blockDim.x + threadIdx.x;
    if (i < 1024) { d_sum[i]=0.f; d_sq[i]=0.f; }
}

// ---- layer-1: pad x [B,3,NP] into d_x16 [B,16,NP] (zeros beyond c=3) ----
__global__ void k_pad16(const float* __restrict__ x) {
    int i = blockIdx.x*256 + threadIdx.x;
    if (i >= B_*16*NP) return;
    int b = i / (16*NP);
    int r = i - b*16*NP;
    int c = r / NP;
    int n = r - c*NP;
    d_x16[i] = (c < 3) ? x[(size_t)b*3*NP + (size_t)c*NP + n] : 0.f;
}

// ---- layer-1 padded weights: d_WG [128][16], rows [0,64)=Wn, [64,128)=Wd ----
__global__ void k_wprep1(const float* __restrict__ W1) {
    int i = blockIdx.x*256 + threadIdx.x;
    if (i >= 128*16) return;
    int o = i >> 4, c = i & 15;
    float v = 0.f;
    if (c < 3) {
        if (o < 64) v = W1[o*6 + c];
        else        v = W1[(o-64)*6 + 3 + c] - W1[(o-64)*6 + c];
    }
    d_WG[i] = v;
}

// ---- build combined weights: rows [0,O) = Wn, rows [O,2O) = W2 - Wn ----
__global__ void k_wprep(const float* __restrict__ W, int O, int C) {
    int i = blockIdx.x*256 + threadIdx.x;
    if (i >= 2*O*C) return;
    int o = i / C, c = i - o*C;
    if (o < O) d_WG[i] = W[(size_t)o*2*C + c];
    else {
        int oo = o - O;
        d_WG[i] = W[(size_t)oo*2*C + C + c] - W[(size_t)oo*2*C + c];
    }
}

// ---- AT GEMM 128x128 / 8x8 (frozen R10 form); src base + batch stride params ----
template<int C, int TWO_O>
__global__ __launch_bounds__(256) void k_atgemm2(const float* srcbase, int bstride, int coff) {
    int b = blockIdx.z;
    int o0 = blockIdx.y*128, n0 = blockIdx.x*128;
    const float* src = srcbase + (size_t)b*bstride + (size_t)coff*NP;
    __shared__ __align__(16) float As[16*128];
    __shared__ __align__(16) float Bs[16*128];
    int tid = threadIdx.x;
    int lrow = tid >> 4, lcol = (tid & 15) * 8;
    int o_l = tid >> 1, kh = (tid & 1) * 8;
    int lane = tid & 31, w = tid >> 5;
    int aoff = (w & 3)*32 + (lane >> 3)*8;
    int boff = (w >> 2)*64 + (lane & 7)*8;
    unsigned long long acc[8][4] = {};
    for (int c0=0;c0<C;c0+=16) {
        float4 w0 = *(const float4*)&d_WG[(size_t)(o0+o_l)*C + c0 + kh];
        float4 w1 = *(const float4*)&d_WG[(size_t)(o0+o_l)*C + c0 + kh + 4];
        As[(kh+0)*128+o_l]=w0.x; As[(kh+1)*128+o_l]=w0.y;
        As[(kh+2)*128+o_l]=w0.z; As[(kh+3)*128+o_l]=w0.w;
        As[(kh+4)*128+o_l]=w1.x; As[(kh+5)*128+o_l]=w1.y;
        As[(kh+6)*128+o_l]=w1.z; As[(kh+7)*128+o_l]=w1.w;
        const float* Sr = src + (size_t)(c0+lrow)*NP;
        *(float4*)&Bs[lrow*128+lcol]   = *(const float4*)&Sr[n0+lcol];
        *(float4*)&Bs[lrow*128+lcol+4] = *(const float4*)&Sr[n0+lcol+4];
        __syncthreads();
        mk_step(As, Bs, aoff, boff, acc);
        __syncthreads();
    }
    float u[8][8];
    #pragma unroll
    for (int i=0;i<8;i++) {
        #pragma unroll
        for (int jp=0;jp<4;jp++) {
            float2 p = upk2(acc[i][jp]);
            u[i][jp*2] = p.x; u[i][jp*2+1] = p.y;
        }
    }
    #pragma unroll
    for (int j=0;j<8;j++) {
        float* dst = &d_AT[((size_t)b*NP + n0 + boff + j)*TWO_O + o0 + aoff];
        *(float4*)dst     = make_float4(u[0][j],u[1][j],u[2][j],u[3][j]);
        *(float4*)(dst+4) = make_float4(u[4][j],u[5][j],u[6][j],u[7][j]);
    }
}

// ---- gather + reduce: mx/sum/sq over 20 neighbors using A table ----
template<int O>
__global__ void k_gather() {
    constexpr int P = 16;
    constexpr int NPG = 256 / O;
    __shared__ int s_ix[P*KNN];
    int tid = threadIdx.x;
    int bn0 = blockIdx.x * P;
    for (int e = tid; e < P*KNN; e += 256) s_ix[e] = d_idx[bn0*KNN + e];
    __syncthreads();
    int pg = tid / O;
    int ol = tid - pg*O;
    float accS = 0.f, accQ = 0.f;
    for (int p = pg; p < P; p += NPG) {
        int bn = bn0 + p;
        int b = bn >> 11;
        size_t jbase = (size_t)b * NP;
        const int* ix = s_ix + p*KNN;
        float m = -3.4e38f, s = 0.f, q = 0.f;
        #pragma unroll
        for (int k=0;k<KNN;k++) {
            float v = d_AT[(jbase + ix[k])*(size_t)(2*O) + ol];
            m = fmaxf(m, v);
            s += v;
            q = fmaf(v, v, q);
        }
        float t = d_AT[(size_t)bn*(2*O) + O + ol];
        d_mx[(size_t)bn*O + ol] = m + t;
        accS += s + 20.f*t;
        accQ += q + 2.f*t*s + 20.f*t*t;
    }
    atomicAdd(&d_sum[ol], accS);
    atomicAdd(&d_sq [ol], accQ);
}

// ---- BN stats -> affine scale/shift per channel ----
__global__ void k_finalize(const float* __restrict__ g, const float* __restrict__ bb,
                           float inv, int O) {
    int o = blockIdx.x*blockDim.x + threadIdx.x;
    if (o >= O) return;
    float mean = d_sum[o]*inv;
    float var  = d_sq[o]*inv - mean*mean;
    float sc = g[o] / sqrtf(var + 1e-5f);
    d_scale[o] = sc;
    d_shift[o] = bb[o] - mean*sc;
}

// ---- apply BN+leaky to max_k and transpose into d_cat slice ----
__global__ void k_apply(int O, int coff) {
    int b = blockIdx.z;
    int n0 = blockIdx.x*32, o0 = blockIdx.y*32;
    __shared__ float tile[32][33];
    #pragma unroll
    for (int q=0;q<4;q++) {
        int n = n0 + threadIdx.y + q*8;
        int o = o0 + threadIdx.x;
        float v = d_mx[((size_t)b*NP + n)*O + o];
        float z = v*d_scale[o] + d_shift[o];
        z = (z > 0.f) ? z : 0.2f*z;
        tile[threadIdx.x][threadIdx.y + q*8] = z;
    }
    __syncthreads();
    #pragma unroll
    for (int q=0;q<4;q++) {
        int o = o0 + threadIdx.y + q*8;
        int n = n0 + threadIdx.x;
        d_cat[((size_t)b*512 + coff + o)*NP + n] = tile[threadIdx.y + q*8][threadIdx.x];
    }
}

// ---- final 512->1024 conv 128x128 / 8x8 with channel stats (frozen R10 form) ----
__global__ __launch_bounds__(256) void k_fgemm2(const float* __restrict__ W5) {
    int b = blockIdx.z;
    int o0 = blockIdx.y*128, n0 = blockIdx.x*128;
    const float* catb = d_cat + (size_t)b*512*NP;
    __shared__ __align__(16) float As[16*128];
    __shared__ __align__(16) float Bs[16*128];
    int tid = threadIdx.x;
    int lrow = tid >> 4, lcol = (tid & 15) * 8;
    int o_l = tid >> 1, kh = (tid & 1) * 8;
    int lane = tid & 31, w = tid >> 5;
    int aoff = (w & 3)*32 + (lane >> 3)*8;
    int boff = (w >> 2)*64 + (lane & 7)*8;
    int ln = lane & 7;
    unsigned long long acc[8][4] = {};
    for (int c0=0;c0<512;c0+=16) {
        float4 w0 = *(const float4*)&W5[(size_t)(o0+o_l)*512 + c0 + kh];
        float4 w1 = *(const float4*)&W5[(size_t)(o0+o_l)*512 + c0 + kh + 4];
        As[(kh+0)*128+o_l]=w0.x; As[(kh+1)*128+o_l]=w0.y;
        As[(kh+2)*128+o_l]=w0.z; As[(kh+3)*128+o_l]=w0.w;
        As[(kh+4)*128+o_l]=w1.x; As[(kh+5)*128+o_l]=w1.y;
        As[(kh+6)*128+o_l]=w1.z; As[(kh+7)*128+o_l]=w1.w;
        const float* Sr = catb + (size_t)(c0+lrow)*NP;
        *(float4*)&Bs[lrow*128+lcol]   = *(const float4*)&Sr[n0+lcol];
        *(float4*)&Bs[lrow*128+lcol+4] = *(const float4*)&Sr[n0+lcol+4];
        __syncthreads();
        mk_step(As, Bs, aoff, boff, acc);
        __syncthreads();
    }
    float s8[8], q8[8];
    #pragma unroll
    for (int i=0;i<8;i++) {
        float2 u0 = upk2(acc[i][0]);
        float2 u1 = upk2(acc[i][1]);
        float2 u2 = upk2(acc[i][2]);
        float2 u3 = upk2(acc[i][3]);
        float vj[8] = {u0.x,u0.y,u1.x,u1.y,u2.x,u2.y,u3.x,u3.y};
        float* dst = &d_Y[((size_t)b*1024 + o0 + aoff + i)*NP + n0 + boff];
        *(float4*)dst     = make_float4(vj[0],vj[1],vj[2],vj[3]);
        *(float4*)(dst+4) = make_float4(vj[4],vj[5],vj[6],vj[7]);
        float s = 0.f, q = 0.f;
        #pragma unroll
        for (int j=0;j<8;j++) { s += vj[j]; q = fmaf(vj[j], vj[j], q); }
        s8[i] = s; q8[i] = q;
    }
    #pragma unroll
    for (int i=0;i<8;i++) {
        #pragma unroll
        for (int off=4;off;off>>=1) {
            s8[i] += __shfl_down_sync(0xffffffffu, s8[i], off, 8);
            q8[i] += __shfl_down_sync(0xffffffffu, q8[i], off, 8);
        }
    }
    if (ln == 0) {
        #pragma unroll
        for (int i=0;i<8;i++) {
            atomicAdd(&d_sum[o0 + aoff + i], s8[i]);
            atomicAdd(&d_sq [o0 + aoff + i], q8[i]);
        }
    }
}

// ---- per (b,o): BN+leaky then max and mean over n ----
__global__ void k_freduce(float* __restrict__ out) {
    int bo = blockIdx.x;
    int b = bo >> 10, o = bo & 1023;
    const float* y = d_Y + (size_t)bo*NP;
    float sc = d_scale[o], sh = d_shift[o];
    int tid = threadIdx.x;
    float mx = -1e30f, s = 0.f;
    #pragma unroll
    for (int q=0;q<8;q++) {
        float z = y[tid + q*256]*sc + sh;
        z = (z > 0.f) ? z : 0.2f*z;
        mx = fmaxf(mx, z); s += z;
    }
    #pragma unroll
    for (int off=16;off;off>>=1) {
        mx = fmaxf(mx, __shfl_down_sync(0xffffffffu, mx, off));
        s += __shfl_down_sync(0xffffffffu, s, off);
    }
    __shared__ float smx[8], ssm[8];
    if ((tid&31)==0) { smx[tid>>5]=mx; ssm[tid>>5]=s; }
    __syncthreads();
    if (tid==0) {
        #pragma unroll
        for (int i=1;i<8;i++){ mx=fmaxf(mx,smx[i]); s+=ssm[i]; }
        out[(size_t)b*2048 + o] = mx;
        out[(size_t)b*2048 + 1024 + o] = s * (1.f/2048.f);
    }
}

// ------------------------------- host -------------------------------
#define GRAM_SMEM (64*129*4 + 256)

__device__ float* dcat_addr_helper();  // (unused)

template<int C, int O>
static void run_edge4(int coff_in, const float* W, const float* g, const float* bb,
                      int coff_out, const float* d_cat_base) {
    dim3 tb(32,8);
    k_norms<<<dim3(NP/256, B_), 256>>>(coff_in, C);
    k_gram2s<C><<<dim3(16, 16, B_), 256, GRAM_SMEM>>>(coff_in);
    k_select<<<B_*NP, 256>>>();
    k_zero<<<4,256>>>();
    k_wprep<<<(2*O*C + 255)/256, 256>>>(W, O, C);
    k_atgemm2<C, 2*O><<<dim3(NP/128, 2*O/128, B_), 256>>>(d_cat_base, 512*NP, coff_in);
    k_gather<O><<<B_*NP/16, 256>>>();
    k_finalize<<<(O+127)/128,128>>>(g, bb, 1.f/(float)(B_*NP*KNN), O);
    k_apply<<<dim3(NP/32, O/32, B_), tb>>>(O, coff_out);
}

extern "C" void kernel_launch(void* const* d_in, const int* in_sizes, int n_in,
                              void* d_out, int out_size) {
    (void)in_sizes; (void)n_in; (void)out_size;
    const float* x  = (const float*)d_in[0];
    const float* W1 = (const float*)d_in[1];
    const float* W2 = (const float*)d_in[2];
    const float* W3 = (const float*)d_in[3];
    const float* W4 = (const float*)d_in[4];
    const float* W5 = (const float*)d_in[5];
    const float* g1 = (const float*)d_in[6];  const float* b1 = (const float*)d_in[7];
    const float* g2 = (const float*)d_in[8];  const float* b2 = (const float*)d_in[9];
    const float* g3 = (const float*)d_in[10]; const float* b3 = (const float*)d_in[11];
    const float* g4 = (const float*)d_in[12]; const float* b4 = (const float*)d_in[13];
    const float* g5 = (const float*)d_in[14]; const float* b5 = (const float*)d_in[15];
    float* out = (float*)d_out;

    const float* cat_base; cudaGetSymbolAddress((void**)&cat_base, d_cat);
    const float* x16_base; cudaGetSymbolAddress((void**)&x16_base, d_x16);

    // ---- layer 1 (C=3): fused select + padded A-table path ----
    {
        dim3 tb(32,8);
        k_pad16<<<(B_*16*NP + 255)/256, 256>>>(x);
        k_select1<<<B_*NP, 256>>>(x);
        k_zero<<<4,256>>>();
        k_wprep1<<<(128*16 + 255)/256, 256>>>(W1);
        k_atgemm2<16, 128><<<dim3(NP/128, 1, B_), 256>>>(x16_base, 16*NP, 0);
        k_gather<64><<<B_*NP/16, 256>>>();
        k_finalize<<<1,128>>>(g1, b1, 1.f/(float)(B_*NP*KNN), 64);
        k_apply<<<dim3(NP/32, 2, B_), tb>>>(64, 0);
    }
    run_edge4<64,  64 >(0,   W2, g2, b2,  64,  cat_base);
    run_edge4<64,  128>(64,  W3, g3, b3, 128, cat_base);
    run_edge4<128, 256>(128, W4, g4, b4, 256, cat_base);

    k_zero<<<4,256>>>();
    k_fgemm2<<<dim3(NP/128, 1024/128, B_), 256>>>(W5);
    k_finalize<<<8,128>>>(g5, b5, 1.f/(float)(B_*NP), 1024);
    k_freduce<<<B_*1024, 256>>>(out);
}